// round 5
// baseline (speedup 1.0000x reference)
#include <cuda_runtime.h>
#include <cstdint>

// ---------------------------------------------------------------------------
#define BATCH 16
#define SEQ_S 1024
#define SEQ_T 2048
#define DIM   512
#define CF    2560
#define MELD  1280

#define TBM 128
#define TBN 128
#define TBK 16
// per-buffer: A 2048 floats (512 f4) + B 2048 floats
#define BUF_FLOATS 4096

// ---------------------------------------------------------------------------
__device__ float g_k  [BATCH * SEQ_S * DIM];
__device__ float g_v  [BATCH * SEQ_S * DIM];
__device__ float g_q  [BATCH * SEQ_T * DIM];
__device__ float g_att[BATCH * SEQ_T * SEQ_S];
__device__ float g_val[BATCH * SEQ_T * DIM];

// ---------------------------------------------------------------------------
__device__ __forceinline__ int get_len(const void* lp, int b) {
    const long long* l8 = (const long long*)lp;
    long long v0 = l8[0];
    if (v0 >= 1 && v0 <= 0x7fffffffLL) return (int)l8[b];
    return ((const int*)lp)[b];
}

__device__ __forceinline__ float ftf32(float x) {
    uint32_t u;
    asm("cvt.rna.tf32.f32 %0, %1;" : "=r"(u) : "f"(x));
    return __uint_as_float(u);
}

// Fragment-permuted float4 indices.
// A value (k, m): m = wm*64 + mi*16 + 8h + g; f4 spans mi.
__device__ __forceinline__ int a_idx(int k, int wm, int h, int g) {
    int slot = (g + ((k & 3) << 1) + (k & 4)) & 7;
    return (((((k << 1) + h) << 1) + wm) << 3) + slot;
}
// B value (k, n): n = wn*32 + ni*8 + g; f4 spans ni. (+wn in slot: conflict-free fill)
__device__ __forceinline__ int b_idx(int k, int wn, int g) {
    int slot = (g + ((k & 3) << 1) + (k & 4) + wn) & 7;
    return ((((k << 2) + wn)) << 3) + slot;
}

// ---------------------------------------------------------------------------
// Unified tf32 GEMM, 128x128x16 tiles, double-buffered, LDS.128 fragments.
//   A_COL: 0 -> A [M,K] row-major; 1 -> A stored [K,M]
//   B_TR : 0 -> B [K,N]; 1 -> B [N,K]
//   EPI  : 0 +bias; 1 *scale; 2 none; 3 mel transposed store (+bias)
// ---------------------------------------------------------------------------
template<int A_COL, int B_TR, int EPI>
__global__ __launch_bounds__(256, 2)
void gemm_tf32(const float* __restrict__ Aall, int lda, long long strideA,
               const float* __restrict__ Ball, int ldb, long long strideB,
               const float* __restrict__ bias,
               float* __restrict__ Call, int ldc, long long strideC,
               int Kdim, float scale) {
    __shared__ __align__(16) float smem[2 * BUF_FLOATS];

    const int z = blockIdx.z;
    const float* A  = Aall + (size_t)z * strideA;
    const float* Bp = Ball + (size_t)z * strideB;
    float* C = Call + (size_t)z * strideC;

    const int bm = blockIdx.y * TBM;
    const int bn = blockIdx.x * TBN;

    const int tid = threadIdx.x;
    const int warp = tid >> 5, lane = tid & 31;
    const int wm = warp & 1, wn = warp >> 1;
    const int g = lane >> 2, tg = lane & 3;

    float4 acc[4][4];
    #pragma unroll
    for (int i = 0; i < 4; i++)
        #pragma unroll
        for (int j = 0; j < 4; j++) acc[i][j] = make_float4(0.f, 0.f, 0.f, 0.f);

    float4 ra[2], rb[2];

    // ---- global load of one k-slice into registers ----
#define LDG_TILE(K0)                                                           \
    {                                                                          \
        if (A_COL == 0) {                                                      \
            int r = tid >> 2, c4 = (tid & 3) << 2;                             \
            ra[0] = *(const float4*)(A + (size_t)(bm + r) * lda + (K0) + c4);  \
            ra[1] = *(const float4*)(A + (size_t)(bm + r + 64) * lda + (K0) + c4); \
        } else {                                                               \
            int kr = tid >> 4, m4 = (tid & 15) << 2;                           \
            ra[0] = *(const float4*)(A + (size_t)((K0) + kr) * lda + bm + m4); \
            ra[1] = *(const float4*)(A + (size_t)((K0) + kr) * lda + bm + m4 + 64); \
        }                                                                      \
        if (B_TR == 0) {                                                       \
            int kr = tid >> 5, n4 = (tid & 31) << 2;                           \
            rb[0] = *(const float4*)(Bp + (size_t)((K0) + kr) * ldb + bn + n4);\
            rb[1] = *(const float4*)(Bp + (size_t)((K0) + kr + 8) * ldb + bn + n4); \
        } else {                                                               \
            int r = tid >> 2, c4 = (tid & 3) << 2;                             \
            rb[0] = *(const float4*)(Bp + (size_t)(bn + r) * ldb + (K0) + c4); \
            rb[1] = *(const float4*)(Bp + (size_t)(bn + r + 64) * ldb + (K0) + c4); \
        }                                                                      \
    }

    // ---- scatter registers into permuted smem (with tf32 convert) ----
#define STS_TILE(DST)                                                          \
    {                                                                          \
        float* As_ = (DST);                                                    \
        float* Bs_ = (DST) + 2048;                                             \
        if (A_COL == 0) {                                                      \
            int r = tid >> 2, c4 = (tid & 3) << 2;                             \
            _Pragma("unroll")                                                  \
            for (int p = 0; p < 2; p++) {                                      \
                int row = r + (p << 6);                                        \
                int wm_ = row >> 6, h_ = (row >> 3) & 1, g_ = row & 7;         \
                int comp = (row >> 4) & 3;                                     \
                const float* v = &ra[p].x;                                     \
                _Pragma("unroll")                                              \
                for (int j = 0; j < 4; j++)                                    \
                    As_[(a_idx(c4 + j, wm_, h_, g_) << 2) + comp] = ftf32(v[j]); \
            }                                                                  \
        } else {                                                               \
            int kr = tid >> 4, m4 = (tid & 15) << 2;                           \
            _Pragma("unroll")                                                  \
            for (int p = 0; p < 2; p++) {                                      \
                const float* v = &ra[p].x;                                     \
                _Pragma("unroll")                                              \
                for (int j = 0; j < 4; j++) {                                  \
                    int m = m4 + (p << 6) + j;                                 \
                    As_[(a_idx(kr, m >> 6, (m >> 3) & 1, m & 7) << 2) +        \
                        ((m >> 4) & 3)] = ftf32(v[j]);                         \
                }                                                              \
            }                                                                  \
        }                                                                      \
        if (B_TR == 0) {                                                       \
            int kr = tid >> 5, n4 = (tid & 31) << 2;                           \
            _Pragma("unroll")                                                  \
            for (int p = 0; p < 2; p++) {                                      \
                int k = kr + (p << 3);                                         \
                const float* v = &rb[p].x;                                     \
                _Pragma("unroll")                                              \
                for (int j = 0; j < 4; j++) {                                  \
                    int n = n4 + j;                                            \
                    Bs_[(b_idx(k, n >> 5, n & 7) << 2) + ((n >> 3) & 3)] =     \
                        ftf32(v[j]);                                           \
                }                                                              \
            }                                                                  \
        } else {                                                               \
            int r = tid >> 2, c4 = (tid & 3) << 2;                             \
            _Pragma("unroll")                                                  \
            for (int p = 0; p < 2; p++) {                                      \
                int n = r + (p << 6);                                          \
                int wn_ = n >> 5, g_ = n & 7, comp = (n >> 3) & 3;             \
                const float* v = &rb[p].x;                                     \
                _Pragma("unroll")                                              \
                for (int j = 0; j < 4; j++)                                    \
                    Bs_[(b_idx(c4 + j, wn_, g_) << 2) + comp] = ftf32(v[j]);   \
            }                                                                  \
        }                                                                      \
    }

    const int nk = Kdim >> 4;

    LDG_TILE(0);
    STS_TILE(smem);
    __syncthreads();

    for (int ks = 0; ks < nk; ks++) {
        float* As = smem + (ks & 1) * BUF_FLOATS;
        float* Bs = As + 2048;

        if (ks + 1 < nk) LDG_TILE((ks + 1) << 4);

        #pragma unroll
        for (int kk = 0; kk < TBK; kk += 8) {
            float av[2][2][4];   // [kh][h][mi]
            float bv[2][4];      // [kh][ni]
            #pragma unroll
            for (int kh = 0; kh < 2; kh++) {
                int k = kk + tg + (kh << 2);
                *(float4*)&av[kh][0][0] = *(const float4*)(As + (a_idx(k, wm, 0, g) << 2));
                *(float4*)&av[kh][1][0] = *(const float4*)(As + (a_idx(k, wm, 1, g) << 2));
                *(float4*)&bv[kh][0]    = *(const float4*)(Bs + (b_idx(k, wn, g) << 2));
            }
            #pragma unroll
            for (int mi = 0; mi < 4; mi++) {
                uint32_t a0 = __float_as_uint(av[0][0][mi]);
                uint32_t a1 = __float_as_uint(av[0][1][mi]);
                uint32_t a2 = __float_as_uint(av[1][0][mi]);
                uint32_t a3 = __float_as_uint(av[1][1][mi]);
                #pragma unroll
                for (int ni = 0; ni < 4; ni++) {
                    uint32_t b0 = __float_as_uint(bv[0][ni]);
                    uint32_t b1 = __float_as_uint(bv[1][ni]);
                    asm volatile(
                        "mma.sync.aligned.m16n8k8.row.col.f32.tf32.tf32.f32 "
                        "{%0,%1,%2,%3}, {%4,%5,%6,%7}, {%8,%9}, {%0,%1,%2,%3};\n"
                        : "+f"(acc[mi][ni].x), "+f"(acc[mi][ni].y),
                          "+f"(acc[mi][ni].z), "+f"(acc[mi][ni].w)
                        : "r"(a0), "r"(a1), "r"(a2), "r"(a3), "r"(b0), "r"(b1));
                }
            }
        }

        if (ks + 1 < nk) {
            float* An = smem + ((ks + 1) & 1) * BUF_FLOATS;
            STS_TILE(An);
            __syncthreads();
        }
    }

    // ---- epilogue ----
    if (EPI != 3) {
        #pragma unroll
        for (int mi = 0; mi < 4; mi++) {
            #pragma unroll
            for (int ni = 0; ni < 4; ni++) {
                int row = bm + wm * 64 + mi * 16 + g;
                int col = bn + wn * 32 + ni * 8 + 2 * tg;
                float4 a = acc[mi][ni];
                if (EPI == 0) {
                    float b0 = bias[col], b1 = bias[col + 1];
                    a.x += b0; a.y += b1; a.z += b0; a.w += b1;
                } else if (EPI == 1) {
                    a.x *= scale; a.y *= scale; a.z *= scale; a.w *= scale;
                }
                C[(size_t)row * ldc + col]           = a.x;
                C[(size_t)row * ldc + col + 1]       = a.y;
                C[(size_t)(row + 8) * ldc + col]     = a.z;
                C[(size_t)(row + 8) * ldc + col + 1] = a.w;
            }
        }
    } else {
        // mel: out[b, n%64, n/64, t]; stage 32-col chunks via smem transpose
        float* sc = smem;  // 32 x 132 = 4224 floats
        #pragma unroll 1
        for (int p = 0; p < 4; p++) {
            __syncthreads();
            if (wn == p) {
                #pragma unroll
                for (int mi = 0; mi < 4; mi++) {
                    #pragma unroll
                    for (int ni = 0; ni < 4; ni++) {
                        int ml = wm * 64 + mi * 16 + g;
                        int nl = ni * 8 + 2 * tg;
                        int ncol = bn + p * 32 + nl;
                        float b0 = bias[ncol], b1 = bias[ncol + 1];
                        float4 a = acc[mi][ni];
                        sc[nl * 132 + ml]           = a.x + b0;
                        sc[(nl + 1) * 132 + ml]     = a.y + b1;
                        sc[nl * 132 + ml + 8]       = a.z + b0;
                        sc[(nl + 1) * 132 + ml + 8] = a.w + b1;
                    }
                }
            }
            __syncthreads();
            int nl = tid >> 3, mq = (tid & 7) << 2;
            int ncol = bn + p * 32 + nl;
            size_t obase = ((size_t)z * 1280 + (size_t)(ncol & 63) * 20 + (ncol >> 6))
                           * (size_t)SEQ_T;
            #pragma unroll
            for (int it = 0; it < 4; it++) {
                int m = mq + it * 32;
                float4 v = *(float4*)(sc + nl * 132 + m);
                *(float4*)(Call + obase + bm + m) = v;
            }
        }
    }
#undef LDG_TILE
#undef STS_TILE
}

// ---------------------------------------------------------------------------
__global__ void softmax_kernel(const void* __restrict__ lengths) {
    int row = blockIdx.x;
    int b = row >> 11;
    float* p = g_att + (size_t)row * SEQ_S;
    int len = get_len(lengths, b);
    int tid = threadIdx.x;

    float4 x = ((const float4*)p)[tid];
    int s0 = tid * 4;

    __shared__ float red_m[8];
    __shared__ float red_s[8];

    float m = -1e30f;
    if (s0 + 0 < len) m = fmaxf(m, x.x);
    if (s0 + 1 < len) m = fmaxf(m, x.y);
    if (s0 + 2 < len) m = fmaxf(m, x.z);
    if (s0 + 3 < len) m = fmaxf(m, x.w);
    #pragma unroll
    for (int o = 16; o > 0; o >>= 1) m = fmaxf(m, __shfl_xor_sync(0xffffffffu, m, o));
    if ((tid & 31) == 0) red_m[tid >> 5] = m;
    __syncthreads();
    if (tid < 32) {
        float mm = (tid < 8) ? red_m[tid] : -1e30f;
        #pragma unroll
        for (int o = 4; o > 0; o >>= 1) mm = fmaxf(mm, __shfl_xor_sync(0xffffffffu, mm, o));
        if (tid == 0) red_m[0] = mm;
    }
    __syncthreads();
    m = red_m[0];

    float e0 = (s0 + 0 < len) ? __expf(x.x - m) : 0.f;
    float e1 = (s0 + 1 < len) ? __expf(x.y - m) : 0.f;
    float e2 = (s0 + 2 < len) ? __expf(x.z - m) : 0.f;
    float e3 = (s0 + 3 < len) ? __expf(x.w - m) : 0.f;
    float s = e0 + e1 + e2 + e3;
    #pragma unroll
    for (int o = 16; o > 0; o >>= 1) s += __shfl_xor_sync(0xffffffffu, s, o);
    if ((tid & 31) == 0) red_s[tid >> 5] = s;
    __syncthreads();
    if (tid < 32) {
        float ss = (tid < 8) ? red_s[tid] : 0.f;
        #pragma unroll
        for (int o = 4; o > 0; o >>= 1) ss += __shfl_xor_sync(0xffffffffu, ss, o);
        if (tid == 0) red_s[0] = ss;
    }
    __syncthreads();
    float inv = 1.0f / red_s[0];

    ((float4*)p)[tid] = make_float4(e0 * inv, e1 * inv, e2 * inv, e3 * inv);
}

// ---------------------------------------------------------------------------
extern "C" void kernel_launch(void* const* d_in, const int* in_sizes, int n_in,
                              void* d_out, int out_size) {
    const float* ph   = (const float*)d_in[0];
    const float* g    = (const float*)d_in[1];
    const void*  lens = d_in[2];
    const float* Wk   = (const float*)d_in[3];
    const float* bk   = (const float*)d_in[4];
    const float* Wv   = (const float*)d_in[5];
    const float* bv   = (const float*)d_in[6];
    const float* Wq   = (const float*)d_in[7];
    const float* bq   = (const float*)d_in[8];
    const float* Wmel = (const float*)d_in[9];
    const float* bmel = (const float*)d_in[10];
    float* out = (float*)d_out;

    float* dk;   cudaGetSymbolAddress((void**)&dk,   g_k);
    float* dv;   cudaGetSymbolAddress((void**)&dv,   g_v);
    float* dq;   cudaGetSymbolAddress((void**)&dq,   g_q);
    float* datt; cudaGetSymbolAddress((void**)&datt, g_att);
    float* dval; cudaGetSymbolAddress((void**)&dval, g_val);

    const float scale = 0.04419417382415922f;  // 1/sqrt(512)
    dim3 blk(256);

    gemm_tf32<0,0,0><<<dim3(4, 128, 1), blk>>>(ph, DIM, 0, Wk, DIM, 0, bk,
                                               dk, DIM, 0, DIM, 1.f);
    gemm_tf32<0,0,0><<<dim3(4, 128, 1), blk>>>(ph, DIM, 0, Wv, DIM, 0, bv,
                                               dv, DIM, 0, DIM, 1.f);
    gemm_tf32<1,0,0><<<dim3(4, 16, BATCH), blk>>>(g, SEQ_T, (long long)CF * SEQ_T,
                                                  Wq, DIM, 0, bq,
                                                  dq, DIM, (long long)SEQ_T * DIM,
                                                  CF, 1.f);
    gemm_tf32<0,1,1><<<dim3(8, 16, BATCH), blk>>>(dq, DIM, (long long)SEQ_T * DIM,
                                                  dk, DIM, (long long)SEQ_S * DIM,
                                                  nullptr,
                                                  datt, SEQ_S, (long long)SEQ_T * SEQ_S,
                                                  DIM, scale);
    softmax_kernel<<<BATCH * SEQ_T, 256>>>(lens);
    gemm_tf32<0,0,2><<<dim3(4, 16, BATCH), blk>>>(datt, SEQ_S, (long long)SEQ_T * SEQ_S,
                                                  dv, DIM, (long long)SEQ_S * DIM,
                                                  nullptr,
                                                  dval, DIM, (long long)SEQ_T * DIM,
                                                  SEQ_S, 1.f);
    gemm_tf32<0,0,3><<<dim3(10, 16, BATCH), blk>>>(dval, DIM, (long long)SEQ_T * DIM,
                                                   Wmel, MELD, 0, bmel,
                                                   out, 0, 0, DIM, 1.f);
}

// round 6
// speedup vs baseline: 1.6661x; 1.6661x over previous
#include <cuda_runtime.h>
#include <cstdint>

// ---------------------------------------------------------------------------
#define BATCH 16
#define SEQ_S 1024
#define SEQ_T 2048
#define DIM   512
#define CF    2560
#define MELD  1280

#define TBM 128
#define TBN 128
#define TBK 16
#define SAS 136      // smem stride (floats) for A rows: conflict-free frag LDS
#define SBS 136
#define BUF_FLOATS (TBK * SAS + TBK * SBS)   // 4352 floats per buffer

// ---------------------------------------------------------------------------
__device__ float g_k  [BATCH * SEQ_S * DIM];
__device__ float g_v  [BATCH * SEQ_S * DIM];
__device__ float g_q  [BATCH * SEQ_T * DIM];
__device__ float g_att[BATCH * SEQ_T * SEQ_S];
__device__ float g_val[BATCH * SEQ_T * DIM];

// ---------------------------------------------------------------------------
__device__ __forceinline__ int get_len(const void* lp, int b) {
    const long long* l8 = (const long long*)lp;
    long long v0 = l8[0];
    if (v0 >= 1 && v0 <= 0x7fffffffLL) return (int)l8[b];
    return ((const int*)lp)[b];
}

__device__ __forceinline__ float ftf32(float x) {
    uint32_t u;
    asm("cvt.rna.tf32.f32 %0, %1;" : "=r"(u) : "f"(x));
    return __uint_as_float(u);
}
__device__ __forceinline__ float4 ftf32_4(float4 v) {
    return make_float4(ftf32(v.x), ftf32(v.y), ftf32(v.z), ftf32(v.w));
}

// ---------------------------------------------------------------------------
// tf32 GEMM, 128x128x16 tiles, 256 thr (2x4 warps, 64x32 warp tile),
// double-buffered: LDG(next) overlaps MMA(current), single sync per slice.
// Layouts identical to the known-good R3 kernel (affine addresses).
//   A_COL: 0 -> A [M,K] row-major; 1 -> A stored [K,M]
//   B_TR : 0 -> B [K,N]; 1 -> B [N,K]
//   EPI  : 0 +bias; 1 *scale; 2 none; 3 mel transposed store (+bias)
// ---------------------------------------------------------------------------
template<int A_COL, int B_TR, int EPI>
__global__ __launch_bounds__(256, 2)
void gemm_tf32(const float* __restrict__ Aall, int lda, long long strideA,
               const float* __restrict__ Ball, int ldb, long long strideB,
               const float* __restrict__ bias,
               float* __restrict__ Call, int ldc, long long strideC,
               int Kdim, float scale) {
    __shared__ __align__(16) float smem[2 * BUF_FLOATS];

    const int z = blockIdx.z;
    const float* A  = Aall + (size_t)z * strideA;
    const float* Bp = Ball + (size_t)z * strideB;
    float* C = Call + (size_t)z * strideC;

    const int bm = blockIdx.y * TBM;
    const int bn = blockIdx.x * TBN;

    const int tid = threadIdx.x;
    const int warp = tid >> 5, lane = tid & 31;
    const int wm = warp & 1, wn = warp >> 1;
    const int g = lane >> 2, tg = lane & 3;

    float4 acc[4][4];
    #pragma unroll
    for (int i = 0; i < 4; i++)
        #pragma unroll
        for (int j = 0; j < 4; j++) acc[i][j] = make_float4(0.f, 0.f, 0.f, 0.f);

    float4 ra[2], rb[2];

    // ---- global load of one k-slice into registers (coalesced float4) ----
#define LDG_TILE(K0)                                                           \
    {                                                                          \
        if (A_COL == 0) {                                                      \
            int r = tid >> 2, c4 = (tid & 3) << 2;                             \
            ra[0] = *(const float4*)(A + (size_t)(bm + r) * lda + (K0) + c4);  \
            ra[1] = *(const float4*)(A + (size_t)(bm + r + 64) * lda + (K0) + c4); \
        } else {                                                               \
            int kr = tid >> 4, m4 = (tid & 15) << 2;                           \
            ra[0] = *(const float4*)(A + (size_t)((K0) + kr) * lda + bm + m4); \
            ra[1] = *(const float4*)(A + (size_t)((K0) + kr) * lda + bm + m4 + 64); \
        }                                                                      \
        if (B_TR == 0) {                                                       \
            int kr = tid >> 5, n4 = (tid & 31) << 2;                           \
            rb[0] = *(const float4*)(Bp + (size_t)((K0) + kr) * ldb + bn + n4);\
            rb[1] = *(const float4*)(Bp + (size_t)((K0) + kr + 8) * ldb + bn + n4); \
        } else {                                                               \
            int r = tid >> 2, c4 = (tid & 3) << 2;                             \
            rb[0] = *(const float4*)(Bp + (size_t)(bn + r) * ldb + (K0) + c4); \
            rb[1] = *(const float4*)(Bp + (size_t)(bn + r + 64) * ldb + (K0) + c4); \
        }                                                                      \
    }

    // ---- store staged registers into smem tile (R3 layout, affine) ----
#define STS_TILE(DST)                                                          \
    {                                                                          \
        float* As_ = (DST);                                                    \
        float* Bs_ = (DST) + TBK * SAS;                                        \
        if (A_COL == 0) {                                                      \
            int r = tid >> 2, c4 = (tid & 3) << 2;                             \
            _Pragma("unroll")                                                  \
            for (int p = 0; p < 2; p++) {                                      \
                int row = r + (p << 6);                                        \
                const float* v = &ra[p].x;                                     \
                _Pragma("unroll")                                              \
                for (int j = 0; j < 4; j++)                                    \
                    As_[(c4 + j) * SAS + row] = ftf32(v[j]);                   \
            }                                                                  \
        } else {                                                               \
            int kr = tid >> 4, m4 = (tid & 15) << 2;                           \
            *(float4*)(As_ + kr * SAS + m4)      = ftf32_4(ra[0]);             \
            *(float4*)(As_ + kr * SAS + m4 + 64) = ftf32_4(ra[1]);             \
        }                                                                      \
        if (B_TR == 0) {                                                       \
            int kr = tid >> 5, n4 = (tid & 31) << 2;                           \
            *(float4*)(Bs_ + kr * SBS + n4)       = ftf32_4(rb[0]);            \
            *(float4*)(Bs_ + (kr + 8) * SBS + n4) = ftf32_4(rb[1]);            \
        } else {                                                               \
            int r = tid >> 2, c4 = (tid & 3) << 2;                             \
            _Pragma("unroll")                                                  \
            for (int p = 0; p < 2; p++) {                                      \
                int n = r + (p << 6);                                          \
                const float* v = &rb[p].x;                                     \
                _Pragma("unroll")                                              \
                for (int j = 0; j < 4; j++)                                    \
                    Bs_[(c4 + j) * SBS + n] = ftf32(v[j]);                     \
            }                                                                  \
        }                                                                      \
    }

    const int nk = Kdim >> 4;

    LDG_TILE(0);
    STS_TILE(smem);
    __syncthreads();

    for (int ks = 0; ks < nk; ks++) {
        const float* As = smem + (ks & 1) * BUF_FLOATS;
        const float* Bs = As + TBK * SAS;

        if (ks + 1 < nk) LDG_TILE((ks + 1) << 4);

        #pragma unroll
        for (int kk = 0; kk < TBK; kk += 8) {
            uint32_t af[4][4], bf[4][2];
            #pragma unroll
            for (int mi = 0; mi < 4; mi++) {
                int m0 = wm * 64 + mi * 16;
                af[mi][0] = __float_as_uint(As[(kk + tg) * SAS + m0 + g]);
                af[mi][1] = __float_as_uint(As[(kk + tg) * SAS + m0 + g + 8]);
                af[mi][2] = __float_as_uint(As[(kk + tg + 4) * SAS + m0 + g]);
                af[mi][3] = __float_as_uint(As[(kk + tg + 4) * SAS + m0 + g + 8]);
            }
            #pragma unroll
            for (int ni = 0; ni < 4; ni++) {
                int n0 = wn * 32 + ni * 8;
                bf[ni][0] = __float_as_uint(Bs[(kk + tg) * SBS + n0 + g]);
                bf[ni][1] = __float_as_uint(Bs[(kk + tg + 4) * SBS + n0 + g]);
            }
            #pragma unroll
            for (int mi = 0; mi < 4; mi++)
                #pragma unroll
                for (int ni = 0; ni < 4; ni++)
                    asm volatile(
                        "mma.sync.aligned.m16n8k8.row.col.f32.tf32.tf32.f32 "
                        "{%0,%1,%2,%3}, {%4,%5,%6,%7}, {%8,%9}, {%0,%1,%2,%3};\n"
                        : "+f"(acc[mi][ni].x), "+f"(acc[mi][ni].y),
                          "+f"(acc[mi][ni].z), "+f"(acc[mi][ni].w)
                        : "r"(af[mi][0]), "r"(af[mi][1]),
                          "r"(af[mi][2]), "r"(af[mi][3]),
                          "r"(bf[ni][0]), "r"(bf[ni][1]));
        }

        if (ks + 1 < nk) {
            STS_TILE(smem + ((ks + 1) & 1) * BUF_FLOATS);
            __syncthreads();
        }
    }

    // ---- epilogue ----
    if (EPI != 3) {
        #pragma unroll
        for (int mi = 0; mi < 4; mi++) {
            #pragma unroll
            for (int ni = 0; ni < 4; ni++) {
                int row = bm + wm * 64 + mi * 16 + g;
                int col = bn + wn * 32 + ni * 8 + 2 * tg;
                float4 a = acc[mi][ni];
                if (EPI == 0) {
                    float b0 = bias[col], b1 = bias[col + 1];
                    a.x += b0; a.y += b1; a.z += b0; a.w += b1;
                } else if (EPI == 1) {
                    a.x *= scale; a.y *= scale; a.z *= scale; a.w *= scale;
                }
                C[(size_t)row * ldc + col]           = a.x;
                C[(size_t)row * ldc + col + 1]       = a.y;
                C[(size_t)(row + 8) * ldc + col]     = a.z;
                C[(size_t)(row + 8) * ldc + col + 1] = a.w;
            }
        }
    } else {
        // mel: out[b, n%64, n/64, t]; stage 32-col chunks via smem transpose
        float* sc = smem;  // 32 x 132 = 4224 floats (fits in buffers)
        #pragma unroll 1
        for (int p = 0; p < 4; p++) {
            __syncthreads();
            if (wn == p) {
                #pragma unroll
                for (int mi = 0; mi < 4; mi++) {
                    #pragma unroll
                    for (int ni = 0; ni < 4; ni++) {
                        int ml = wm * 64 + mi * 16 + g;
                        int nl = ni * 8 + 2 * tg;
                        int ncol = bn + p * 32 + nl;
                        float b0 = bias[ncol], b1 = bias[ncol + 1];
                        float4 a = acc[mi][ni];
                        sc[nl * 132 + ml]           = a.x + b0;
                        sc[(nl + 1) * 132 + ml]     = a.y + b1;
                        sc[nl * 132 + ml + 8]       = a.z + b0;
                        sc[(nl + 1) * 132 + ml + 8] = a.w + b1;
                    }
                }
            }
            __syncthreads();
            int nl = tid >> 3, mq = (tid & 7) << 2;
            int ncol = bn + p * 32 + nl;
            size_t obase = ((size_t)z * 1280 + (size_t)(ncol & 63) * 20 + (ncol >> 6))
                           * (size_t)SEQ_T;
            #pragma unroll
            for (int it = 0; it < 4; it++) {
                int m = mq + it * 32;
                float4 v = *(float4*)(sc + nl * 132 + m);
                *(float4*)(Call + obase + bm + m) = v;
            }
        }
    }
#undef LDG_TILE
#undef STS_TILE
}

// ---------------------------------------------------------------------------
__global__ void softmax_kernel(const void* __restrict__ lengths) {
    int row = blockIdx.x;
    int b = row >> 11;
    float* p = g_att + (size_t)row * SEQ_S;
    int len = get_len(lengths, b);
    int tid = threadIdx.x;

    float4 x = ((const float4*)p)[tid];
    int s0 = tid * 4;

    __shared__ float red_m[8];
    __shared__ float red_s[8];

    float m = -1e30f;
    if (s0 + 0 < len) m = fmaxf(m, x.x);
    if (s0 + 1 < len) m = fmaxf(m, x.y);
    if (s0 + 2 < len) m = fmaxf(m, x.z);
    if (s0 + 3 < len) m = fmaxf(m, x.w);
    #pragma unroll
    for (int o = 16; o > 0; o >>= 1) m = fmaxf(m, __shfl_xor_sync(0xffffffffu, m, o));
    if ((tid & 31) == 0) red_m[tid >> 5] = m;
    __syncthreads();
    if (tid < 32) {
        float mm = (tid < 8) ? red_m[tid] : -1e30f;
        #pragma unroll
        for (int o = 4; o > 0; o >>= 1) mm = fmaxf(mm, __shfl_xor_sync(0xffffffffu, mm, o));
        if (tid == 0) red_m[0] = mm;
    }
    __syncthreads();
    m = red_m[0];

    float e0 = (s0 + 0 < len) ? __expf(x.x - m) : 0.f;
    float e1 = (s0 + 1 < len) ? __expf(x.y - m) : 0.f;
    float e2 = (s0 + 2 < len) ? __expf(x.z - m) : 0.f;
    float e3 = (s0 + 3 < len) ? __expf(x.w - m) : 0.f;
    float s = e0 + e1 + e2 + e3;
    #pragma unroll
    for (int o = 16; o > 0; o >>= 1) s += __shfl_xor_sync(0xffffffffu, s, o);
    if ((tid & 31) == 0) red_s[tid >> 5] = s;
    __syncthreads();
    if (tid < 32) {
        float ss = (tid < 8) ? red_s[tid] : 0.f;
        #pragma unroll
        for (int o = 4; o > 0; o >>= 1) ss += __shfl_xor_sync(0xffffffffu, ss, o);
        if (tid == 0) red_s[0] = ss;
    }
    __syncthreads();
    float inv = 1.0f / red_s[0];

    ((float4*)p)[tid] = make_float4(e0 * inv, e1 * inv, e2 * inv, e3 * inv);
}

// ---------------------------------------------------------------------------
extern "C" void kernel_launch(void* const* d_in, const int* in_sizes, int n_in,
                              void* d_out, int out_size) {
    const float* ph   = (const float*)d_in[0];
    const float* g    = (const float*)d_in[1];
    const void*  lens = d_in[2];
    const float* Wk   = (const float*)d_in[3];
    const float* bk   = (const float*)d_in[4];
    const float* Wv   = (const float*)d_in[5];
    const float* bv   = (const float*)d_in[6];
    const float* Wq   = (const float*)d_in[7];
    const float* bq   = (const float*)d_in[8];
    const float* Wmel = (const float*)d_in[9];
    const float* bmel = (const float*)d_in[10];
    float* out = (float*)d_out;

    float* dk;   cudaGetSymbolAddress((void**)&dk,   g_k);
    float* dv;   cudaGetSymbolAddress((void**)&dv,   g_v);
    float* dq;   cudaGetSymbolAddress((void**)&dq,   g_q);
    float* datt; cudaGetSymbolAddress((void**)&datt, g_att);
    float* dval; cudaGetSymbolAddress((void**)&dval, g_val);

    const float scale = 0.04419417382415922f;  // 1/sqrt(512)
    dim3 blk(256);

    gemm_tf32<0,0,0><<<dim3(4, 128, 1), blk>>>(ph, DIM, 0, Wk, DIM, 0, bk,
                                               dk, DIM, 0, DIM, 1.f);
    gemm_tf32<0,0,0><<<dim3(4, 128, 1), blk>>>(ph, DIM, 0, Wv, DIM, 0, bv,
                                               dv, DIM, 0, DIM, 1.f);
    gemm_tf32<1,0,0><<<dim3(4, 16, BATCH), blk>>>(g, SEQ_T, (long long)CF * SEQ_T,
                                                  Wq, DIM, 0, bq,
                                                  dq, DIM, (long long)SEQ_T * DIM,
                                                  CF, 1.f);
    gemm_tf32<0,1,1><<<dim3(8, 16, BATCH), blk>>>(dq, DIM, (long long)SEQ_T * DIM,
                                                  dk, DIM, (long long)SEQ_S * DIM,
                                                  nullptr,
                                                  datt, SEQ_S, (long long)SEQ_T * SEQ_S,
                                                  DIM, scale);
    softmax_kernel<<<BATCH * SEQ_T, 256>>>(lens);
    gemm_tf32<0,0,2><<<dim3(4, 16, BATCH), blk>>>(datt, SEQ_S, (long long)SEQ_T * SEQ_S,
                                                  dv, DIM, (long long)SEQ_S * DIM,
                                                  nullptr,
                                                  dval, DIM, (long long)SEQ_T * DIM,
                                                  SEQ_S, 1.f);
    gemm_tf32<0,0,3><<<dim3(10, 16, BATCH), blk>>>(dval, DIM, (long long)SEQ_T * DIM,
                                                   Wmel, MELD, 0, bmel,
                                                   out, 0, 0, DIM, 1.f);
}